// round 6
// baseline (speedup 1.0000x reference)
#include <cuda_runtime.h>
#include <cstdint>
#include <cstddef>

// 2-layer LSTM, B=512 T=1024 I=80 H=160, fp32, persistent 8-CTA-cluster kernel.
// 16 clusters x 8 ranks. Cluster owns 32 batch elems; rank owns 20 h-rows
// (80 gate rows/layer) with all weight slices SMEM-resident. h0/h1 replicated
// per rank, refreshed each step via st.shared::cluster.

#define HDIM   160
#define IDIM   80
#define BATCHN 512
#define TSTEPS 1024
#define CLUSTER 8
#define HS 20          // h rows per rank
#define GS 80          // gate rows per rank (4*HS)
#define NB 32          // batch per cluster
#define NTH 320        // 10 warps: warp w owns slice rows {2w, 2w+1}
#define NCLUS 16
#define GRIDN (NCLUS*CLUSTER)
#define XSTR 33        // padded x-tile stride (conflict-free STS + LDS)

// shared memory layout (float offsets)
#define OFF_W0   0        // W_hh0 slice [GS][HDIM]
#define OFF_WI1  12800    // W_ih1 slice [GS][HDIM]
#define OFF_WH1  25600    // W_hh1 slice [GS][HDIM]
#define OFF_WI0  38400    // W_ih0 slice [GS][IDIM]
#define OFF_H0   44800    // h0 replica [HDIM][NB]
#define OFF_H1   49920    // h1 replica [HDIM][NB]
#define OFF_XS   55040    // x tile [IDIM][XSTR] (transposed, padded)
#define OFF_B0   57680    // fused bias layer0 slice [GS]
#define OFF_B1   57760    // fused bias layer1 slice [GS]
#define OFF_WOUT 57840    // W_out [HDIM]
#define OFF_BOUT 58000
#define SMEM_FLOATS 58004
#define SMEM_BYTES (SMEM_FLOATS*4)   // 232016 B <= 232448 max dyn smem

__device__ __forceinline__ uint32_t smem_u32(const void* p){
    uint32_t a;
    asm("{ .reg .u64 t; cvta.to.shared.u64 t, %1; cvt.u32.u64 %0, t; }"
        : "=r"(a) : "l"(p));
    return a;
}
__device__ __forceinline__ uint32_t mapa_rank(uint32_t addr, uint32_t r){
    uint32_t d;
    asm("mapa.shared::cluster.u32 %0, %1, %2;" : "=r"(d) : "r"(addr), "r"(r));
    return d;
}
__device__ __forceinline__ void st_cluster_f32(uint32_t addr, float v){
    asm volatile("st.shared::cluster.f32 [%0], %1;" :: "r"(addr), "f"(v));
}
__device__ __forceinline__ void cluster_sync_all(){
    asm volatile("barrier.cluster.arrive.aligned;" ::: "memory");
    asm volatile("barrier.cluster.wait.aligned;"   ::: "memory");
}
__device__ __forceinline__ uint32_t ctarank(){
    uint32_t r; asm("mov.u32 %0, %%cluster_ctarank;" : "=r"(r)); return r;
}
__device__ __forceinline__ float sigmoidf_(float x){
    return 1.0f / (1.0f + expf(-x));
}

// acc[2q+p] += sum_k W[(q*HS + r0 + p)*K + k] * hp[k*STR]
// W loads warp-uniform LDS.128 (broadcast); hp loads lane-consecutive.
template<int K, int STR>
__device__ __forceinline__ void mm8(float acc[8], const float* __restrict__ Wsm,
                                    int r0, const float* __restrict__ hp){
    const float4* Wr[8];
    #pragma unroll
    for (int q = 0; q < 4; q++){
        Wr[2*q]   = reinterpret_cast<const float4*>(Wsm + (q*HS + r0    )*K);
        Wr[2*q+1] = reinterpret_cast<const float4*>(Wsm + (q*HS + r0 + 1)*K);
    }
    #pragma unroll 2
    for (int kk = 0; kk < K/4; kk++){
        float h0 = hp[(4*kk+0)*STR];
        float h1 = hp[(4*kk+1)*STR];
        float h2 = hp[(4*kk+2)*STR];
        float h3 = hp[(4*kk+3)*STR];
        #pragma unroll
        for (int r = 0; r < 8; r++){
            float4 wv = Wr[r][kk];
            acc[r] = fmaf(wv.x, h0, acc[r]);
            acc[r] = fmaf(wv.y, h1, acc[r]);
            acc[r] = fmaf(wv.z, h2, acc[r]);
            acc[r] = fmaf(wv.w, h3, acc[r]);
        }
    }
}

__global__ void __cluster_dims__(CLUSTER,1,1) __launch_bounds__(NTH,1)
lstm2_kernel(const float* __restrict__ x,
             const float* __restrict__ Wih0, const float* __restrict__ Whh0,
             const float* __restrict__ bih0, const float* __restrict__ bhh0,
             const float* __restrict__ Wih1, const float* __restrict__ Whh1,
             const float* __restrict__ bih1, const float* __restrict__ bhh1,
             const float* __restrict__ Wout, const float* __restrict__ bout,
             float* __restrict__ out)
{
    extern __shared__ float sm[];
    const int tid  = threadIdx.x;
    const int lane = tid & 31;
    const int w    = tid >> 5;        // warp 0..9
    const int r0   = 2*w;             // local slice rows r0, r0+1
    const uint32_t rank = ctarank();
    const int cidx = blockIdx.x / CLUSTER;
    const int b0g  = cidx * NB;       // global batch base of cluster
    const int hb   = (int)rank * HS;  // global h-row base of this rank

    // ---- persistent weight slices -> SMEM ----
    for (int idx = tid; idx < GS*HDIM; idx += NTH){
        int lr = idx / HDIM, k = idx - lr*HDIM;
        int q = lr / HS, j = lr - q*HS;
        int grow = q*HDIM + hb + j;           // pytorch gate order i,f,g,o
        sm[OFF_W0  + idx] = Whh0[grow*HDIM + k];
        sm[OFF_WI1 + idx] = Wih1[grow*HDIM + k];
        sm[OFF_WH1 + idx] = Whh1[grow*HDIM + k];
    }
    for (int idx = tid; idx < GS*IDIM; idx += NTH){
        int lr = idx / IDIM, k = idx - lr*IDIM;
        int q = lr / HS, j = lr - q*HS;
        int grow = q*HDIM + hb + j;
        sm[OFF_WI0 + idx] = Wih0[grow*IDIM + k];
    }
    for (int idx = tid; idx < GS; idx += NTH){
        int q = idx / HS, j = idx - q*HS;
        int grow = q*HDIM + hb + j;
        sm[OFF_B0 + idx] = bih0[grow] + bhh0[grow];
        sm[OFF_B1 + idx] = bih1[grow] + bhh1[grow];
    }
    for (int idx = tid; idx < HDIM; idx += NTH) sm[OFF_WOUT + idx] = Wout[idx];
    if (tid == 0) sm[OFF_BOUT] = bout[0];
    for (int idx = tid; idx < HDIM*NB; idx += NTH){
        sm[OFF_H0 + idx] = 0.0f;
        sm[OFF_H1 + idx] = 0.0f;
    }
    float c0a = 0.f, c0b = 0.f, c1a = 0.f, c1b = 0.f;
    cluster_sync_all();

    // shared addresses of this thread's h entries (for cluster broadcast)
    const uint32_t a0  = smem_u32(&sm[OFF_H0 + (hb + r0)*NB + lane]);
    const uint32_t a0b = a0 + NB*4;
    const uint32_t a1  = smem_u32(&sm[OFF_H1 + (hb + r0)*NB + lane]);
    const uint32_t a1b = a1 + NB*4;

    const float* __restrict__ xg = x + (size_t)b0g * TSTEPS * IDIM;

    for (int t = 0; t < TSTEPS; t++){
        // x_t tile -> SMEM transposed [i][b] with pad-33 (coalesced LDG,
        // conflict-free STS)
        for (int idx = tid; idx < NB*IDIM; idx += NTH){
            int b = idx / IDIM, i = idx - b*IDIM;
            sm[OFF_XS + i*XSTR + b] = xg[(size_t)b*TSTEPS*IDIM + (size_t)t*IDIM + i];
        }
        __syncthreads();

        // ---- layer 0 gates ----
        float acc[8];
        #pragma unroll
        for (int q = 0; q < 4; q++){
            acc[2*q]   = sm[OFF_B0 + q*HS + r0];
            acc[2*q+1] = sm[OFF_B0 + q*HS + r0 + 1];
        }
        mm8<IDIM, XSTR>(acc, &sm[OFF_WI0], r0, &sm[OFF_XS] + lane);
        mm8<HDIM, NB  >(acc, &sm[OFF_W0 ], r0, &sm[OFF_H0] + lane);

        float hn0, hn1;
        {
            float ig = sigmoidf_(acc[0]), fg = sigmoidf_(acc[2]);
            float gg = tanhf(acc[4]),     og = sigmoidf_(acc[6]);
            c0a = fg*c0a + ig*gg;
            hn0 = og * tanhf(c0a);
            ig = sigmoidf_(acc[1]); fg = sigmoidf_(acc[3]);
            gg = tanhf(acc[5]);     og = sigmoidf_(acc[7]);
            c0b = fg*c0b + ig*gg;
            hn1 = og * tanhf(c0b);
        }
        cluster_sync_all();              // all ranks done reading old h0
        #pragma unroll
        for (uint32_t r = 0; r < CLUSTER; r++){
            st_cluster_f32(mapa_rank(a0 , r), hn0);
            st_cluster_f32(mapa_rank(a0b, r), hn1);
        }
        cluster_sync_all();              // new h0 visible everywhere

        // ---- layer 1 gates ----
        float acc1[8];
        #pragma unroll
        for (int q = 0; q < 4; q++){
            acc1[2*q]   = sm[OFF_B1 + q*HS + r0];
            acc1[2*q+1] = sm[OFF_B1 + q*HS + r0 + 1];
        }
        mm8<HDIM, NB>(acc1, &sm[OFF_WI1], r0, &sm[OFF_H0] + lane);
        mm8<HDIM, NB>(acc1, &sm[OFF_WH1], r0, &sm[OFF_H1] + lane);
        {
            float ig = sigmoidf_(acc1[0]), fg = sigmoidf_(acc1[2]);
            float gg = tanhf(acc1[4]),     og = sigmoidf_(acc1[6]);
            c1a = fg*c1a + ig*gg;
            hn0 = og * tanhf(c1a);
            ig = sigmoidf_(acc1[1]); fg = sigmoidf_(acc1[3]);
            gg = tanhf(acc1[5]);     og = sigmoidf_(acc1[7]);
            c1b = fg*c1b + ig*gg;
            hn1 = og * tanhf(c1b);
        }
        cluster_sync_all();              // all ranks done reading old h1
        #pragma unroll
        for (uint32_t r = 0; r < CLUSTER; r++){
            st_cluster_f32(mapa_rank(a1 , r), hn0);
            st_cluster_f32(mapa_rank(a1b, r), hn1);
        }
        cluster_sync_all();              // new h1 visible everywhere

        // ---- output head: warp 0, lane = batch ----
        if (w == 0){
            float s0 = 0.f, s1 = 0.f, s2 = 0.f, s3 = 0.f;
            #pragma unroll
            for (int k = 0; k < HDIM; k += 4){
                s0 = fmaf(sm[OFF_WOUT + k    ], sm[OFF_H1 + (k    )*NB + lane], s0);
                s1 = fmaf(sm[OFF_WOUT + k + 1], sm[OFF_H1 + (k + 1)*NB + lane], s1);
                s2 = fmaf(sm[OFF_WOUT + k + 2], sm[OFF_H1 + (k + 2)*NB + lane], s2);
                s3 = fmaf(sm[OFF_WOUT + k + 3], sm[OFF_H1 + (k + 3)*NB + lane], s3);
            }
            float y = (s0 + s1) + (s2 + s3) + sm[OFF_BOUT];
            out[(size_t)(b0g + lane)*TSTEPS + t] = fmaxf(y, 0.0f);
        }
    }
}

extern "C" void kernel_launch(void* const* d_in, const int* in_sizes, int n_in,
                              void* d_out, int out_size) {
    (void)in_sizes; (void)n_in; (void)out_size;
    const float* x    = (const float*)d_in[0];
    const float* Wih0 = (const float*)d_in[1];
    const float* Whh0 = (const float*)d_in[2];
    const float* bih0 = (const float*)d_in[3];
    const float* bhh0 = (const float*)d_in[4];
    const float* Wih1 = (const float*)d_in[5];
    const float* Whh1 = (const float*)d_in[6];
    const float* bih1 = (const float*)d_in[7];
    const float* bhh1 = (const float*)d_in[8];
    const float* Wout = (const float*)d_in[9];
    const float* bout = (const float*)d_in[10];
    float* out = (float*)d_out;

    cudaFuncSetAttribute(lstm2_kernel,
                         cudaFuncAttributeMaxDynamicSharedMemorySize, SMEM_BYTES);
    lstm2_kernel<<<GRIDN, NTH, SMEM_BYTES>>>(x, Wih0, Whh0, bih0, bhh0,
                                             Wih1, Whh1, bih1, bhh1,
                                             Wout, bout, out);
}